// round 15
// baseline (speedup 1.0000x reference)
#include <cuda_runtime.h>
#include <cuda_bf16.h>
#include <cstdint>

#define NB 2
#define MID 64
#define BAND 8
#define HS 96
#define HQ 384
#define HQP 385
#define LTOT 576
#define PP 25
#define QW 96
#define QPOS (QW*QW)
#define MTOT 9216

// scores GEMM tiling (cp.async A from precomputed k-major g_A), 512 threads
#define GM_M 128
#define GM_N 192
#define KHALF 1600
#define KROW 3200
#define SCHUNK 25

// scores smem per stage: Ahi 16K | Alo 16K | Bhi 24K | Blo 24K
#define S2_ALO 16384
#define S2_BHI 32768
#define S2_BLO 57344
#define S2_STAGE 81920
#define S2_TOTAL (2*S2_STAGE)

// out GEMM (fused softmax; A resident 18x8KB, B double-buffered)
#define G2_M 64
#define G2_N 256
#define AK 1152
#define G2_NCHUNK 27
#define OM_B 147456
#define OM_BSTAGE 32768
#define OM_TOTAL (OM_B + 2*OM_BSTAGE)

// ---------------- scratch (device globals; no runtime allocation) ------------
__device__ float g_kfea[NB*MID*HS*HS];
__device__ int   g_maxssq[NB];
__device__ float g_attn[NB*QPOS*LTOT];        // f32 scores (pre-softmax)
__device__ __nv_bfloat16 g_A[(size_t)NB*KROW*MTOT];   // 118 MB, k-major [n][k][m]
__device__ __nv_bfloat16 g_B[(size_t)NB*LTOT*KROW];   // keys [n][l][hi1600|lo1600]
__device__ __nv_bfloat16 g_vb[(size_t)NB*G2_N*AK];    // [n][b*25+p][hi|lo]
__device__ float g_out2[(size_t)NB*QPOS*G2_N];

__device__ __forceinline__ float lrelu(float v) { return v > 0.f ? v : 0.01f * v; }

__device__ __forceinline__ uint32_t smem_u32(const void* p) {
    uint32_t a;
    asm("{ .reg .u64 t; cvta.to.shared.u64 t, %1; cvt.u32.u64 %0, t; }" : "=r"(a) : "l"(p));
    return a;
}
__device__ __forceinline__ void cp16(uint32_t dst, const void* src) {
    asm volatile("cp.async.cg.shared.global [%0], [%1], 16;" :: "r"(dst), "l"(src));
}
__device__ __forceinline__ void sts16(uint32_t addr, uint16_t v) {
    asm volatile("st.shared.u16 [%0], %1;" :: "r"(addr), "h"(v));
}
__device__ __forceinline__ void ldsm4(uint32_t* r, uint32_t a) {
    asm volatile("ldmatrix.sync.aligned.m8n8.x4.shared.b16 {%0,%1,%2,%3}, [%4];"
                 : "=r"(r[0]), "=r"(r[1]), "=r"(r[2]), "=r"(r[3]) : "r"(a));
}
__device__ __forceinline__ void ldsm4t(uint32_t* r, uint32_t a) {
    asm volatile("ldmatrix.sync.aligned.m8n8.x4.trans.shared.b16 {%0,%1,%2,%3}, [%4];"
                 : "=r"(r[0]), "=r"(r[1]), "=r"(r[2]), "=r"(r[3]) : "r"(a));
}
__device__ __forceinline__ void mma_bf16(float* c, const uint32_t* a, uint32_t b0, uint32_t b1) {
    asm volatile("mma.sync.aligned.m16n8k16.row.col.f32.bf16.bf16.f32 "
                 "{%0,%1,%2,%3}, {%4,%5,%6,%7}, {%8,%9}, {%0,%1,%2,%3};"
                 : "+f"(c[0]), "+f"(c[1]), "+f"(c[2]), "+f"(c[3])
                 : "r"(a[0]), "r"(a[1]), "r"(a[2]), "r"(a[3]), "r"(b0), "r"(b1));
}
#define SWZB(o) ((o) ^ (((o) >> 3) & 0x70))           // 128B rows
#define SWZA(o) ((o) ^ ((((o) >> 8) & 7) << 4))       // 256B rows

// ---------------- 3x3 conv, 1 -> C channels -----------------------------------
template<int C, int HIN, int HOUT>
__global__ void conv_1toC(const float* __restrict__ in, const float* __restrict__ w,
                          const float* __restrict__ bias, float* __restrict__ out) {
    __shared__ float sw[C*9];
    __shared__ float sb[C];
    int t = threadIdx.x;
    for (int e = t; e < C*9; e += blockDim.x) sw[e] = w[e];
    for (int e = t; e < C;   e += blockDim.x) sb[e] = bias[e];
    __syncthreads();
    int idx = blockIdx.x * blockDim.x + t;
    int n = blockIdx.y;
    if (idx >= HOUT*HOUT) return;
    int y = idx / HOUT, x = idx % HOUT;
    bool inside = (y < HIN) && (x < HIN);
    float v[9];
#pragma unroll
    for (int dy = 0; dy < 3; dy++)
#pragma unroll
        for (int dx = 0; dx < 3; dx++) {
            int yy = y + dy - 1, xx = x + dx - 1;
            v[dy*3+dx] = (inside && yy >= 0 && yy < HIN && xx >= 0 && xx < HIN)
                         ? in[(n*HIN + yy)*HIN + xx] : 0.f;
        }
#pragma unroll 8
    for (int c = 0; c < C; c++) {
        float s = 0.f;
        if (inside) {
            s = sb[c];
#pragma unroll
            for (int k = 0; k < 9; k++) s += v[k] * sw[c*9 + k];
            s = lrelu(s);
        }
        out[((n*C + c)*HOUT + y)*HOUT + x] = s;
    }
}

// ---------------- fused prep: build_b (keys) + [q-conv + im2col] (A matrix) -----
__global__ void prep_kernel(const float* __restrict__ pan,
                            const float* __restrict__ wq,
                            const float* __restrict__ bq) {
    __shared__ float sq[4][5][388];
    __shared__ float span[7][388];
    __shared__ float swq[4][9];
    __shared__ float sbq[4];
    int bid = blockIdx.x;
    int t = threadIdx.x;
    if (bid < NB*MID) {
        if (bid == 0 && t < NB) g_maxssq[t] = 0;
        int n = bid >> 6, c = bid & 63;
        const float* src = g_kfea + ((size_t)(n*MID + c))*HS*HS;
        for (int l = t; l < LTOT; l += 512) {
            int py = l / 24, px = l % 24;
            __nv_bfloat16* dst = g_B + ((size_t)(n*LTOT) + l)*KROW + c*PP;
#pragma unroll
            for (int p = 0; p < PP; p++) {
                int i = p / 5, j = p % 5;
                int sy = 4*py + i - 2; if (sy < 0) sy += 97;
                int sx = 4*px + j - 2; if (sx < 0) sx += 97;
                float v = 0.f;
                if (sy < HS && sx < HS) v = src[sy*HS + sx];
                __nv_bfloat16 h = __float2bfloat16(v);
                dst[p] = h;
                dst[KHALF + p] = __float2bfloat16(v - __bfloat162float(h));
            }
        }
    } else {
        int rem = bid - NB*MID;
        int n  = rem / (16*QW);
        int r2 = rem % (16*QW);
        int cg = r2 / QW;
        int oy = r2 % QW;

        if (t < 36) swq[t / 9][t % 9] = wq[(cg*4)*9 + t];
        else if (t < 40) sbq[t - 36] = bq[cg*4 + t - 36];

        const float* pn = pan + (size_t)n*HQ*HQ;
        int y0 = 4*oy - 1;
        for (int e = t; e < 7*388; e += 512) {
            int rr = e / 388, xx = e % 388;
            int gy = y0 + rr, gx = xx - 1;
            float v = 0.f;
            if (gy >= 0 && gy < HQ && gx >= 0 && gx < HQ) v = pn[(size_t)gy*HQ + gx];
            span[rr][xx] = v;
        }
        __syncthreads();

        for (int e = t; e < 4*5*385; e += 512) {
            int c = e / 1925, r3 = e % 1925, r = r3 / 385, x = r3 % 385;
            float v = 0.f;
            if (x < HQ && (4*oy + r) < HQ) {
                float s = sbq[c];
#pragma unroll
                for (int dy = 0; dy < 3; dy++)
#pragma unroll
                    for (int dx = 0; dx < 3; dx++)
                        s += span[r + dy][x + dx] * swq[c][dy*3 + dx];
                v = lrelu(s);
            }
            sq[c][r][x] = v;
        }
        __syncthreads();

        for (int e = t; e < 200*48; e += 512) {
            int row = e / 48, u = e % 48;
            int c = row / 50, r3 = row % 50;
            int half = r3 / 25, p = r3 % 25;
            int i = p / 5, j = p % 5;
            float v0 = sq[c][i][8*u + j];
            float v1 = sq[c][i][8*u + 4 + j];
            __nv_bfloat16 h0 = __float2bfloat16(v0);
            __nv_bfloat16 h1 = __float2bfloat16(v1);
            uint32_t pack;
            if (half == 0) {
                pack = (uint32_t)__bfloat16_as_ushort(h0) |
                       ((uint32_t)__bfloat16_as_ushort(h1) << 16);
            } else {
                __nv_bfloat16 l0 = __float2bfloat16(v0 - __bfloat162float(h0));
                __nv_bfloat16 l1 = __float2bfloat16(v1 - __bfloat162float(h1));
                pack = (uint32_t)__bfloat16_as_ushort(l0) |
                       ((uint32_t)__bfloat16_as_ushort(l1) << 16);
            }
            size_t krow = (size_t)n*KROW + half*KHALF + (cg*4 + c)*PP + p;
            reinterpret_cast<uint32_t*>(g_A)[krow*(MTOT/2) + oy*48 + u] = pack;
        }
    }
}

// ---------------- V: fused 3x3 conv + patch gather -> bf16 hi/lo ----------------
__global__ void gather_v_fused(const float* __restrict__ ms,
                               const float* __restrict__ wv,
                               const float* __restrict__ bv) {
    __shared__ float sw[BAND*9];
    __shared__ float sbv;
    int bid = blockIdx.x;                 // n*200 + b*25 + p
    int n  = bid / (BAND*PP);
    int bp = bid % (BAND*PP);
    int b  = bp / PP;
    int p  = bp % PP;
    int i  = p / 5, j = p % 5;
    int l  = threadIdx.x;
    if (l < BAND*9) sw[l] = wv[b*BAND*9 + l];
    if (l == BAND*9) sbv = bv[b];
    __syncthreads();

    int py = l / 24, px = l % 24;
    int sy = 4*py + i - 2; if (sy < 0) sy += 97;
    int sx = 4*px + j - 2; if (sx < 0) sx += 97;
    float v = 0.f;
    if (sy < HS && sx < HS) {
        float s = sbv;
        const float* mn = ms + (size_t)n*BAND*HS*HS;
#pragma unroll
        for (int ci = 0; ci < BAND; ci++) {
            const float* ip = mn + (size_t)ci*HS*HS;
#pragma unroll
            for (int dy = 0; dy < 3; dy++) {
                int yy = sy + dy - 1;
                if (yy < 0 || yy >= HS) continue;
#pragma unroll
                for (int dx = 0; dx < 3; dx++) {
                    int xx = sx + dx - 1;
                    if (xx < 0 || xx >= HS) continue;
                    s += __ldg(&ip[yy*HS + xx]) * sw[ci*9 + dy*3 + dx];
                }
            }
        }
        v = lrelu(s);
    }
    __nv_bfloat16 h = __float2bfloat16(v);
    __nv_bfloat16* dst = g_vb + ((size_t)(n*G2_N) + bp)*AK;
    dst[l] = h;
    dst[LTOT + l] = __float2bfloat16(v - __bfloat162float(h));
}

// ---------------- per-patch ssq from g_B (hi+lo) + atomic max ---------------------
__global__ void ssq_b() {
    __shared__ float red[4];
    int row = blockIdx.x;
    int t = threadIdx.x;
    const uint4* rp = reinterpret_cast<const uint4*>(g_B + (size_t)row*KROW);
    float s = 0.f;
    for (int e = t; e < 200; e += 128) {
        uint4 hi = __ldg(&rp[e]);
        uint4 lo = __ldg(&rp[200 + e]);
        const uint32_t* hw = &hi.x;
        const uint32_t* lw = &lo.x;
#pragma unroll
        for (int q = 0; q < 4; q++) {
            float2 fh = __bfloat1622float2(*reinterpret_cast<const __nv_bfloat162*>(&hw[q]));
            float2 fl = __bfloat1622float2(*reinterpret_cast<const __nv_bfloat162*>(&lw[q]));
            float v0 = fh.x + fl.x, v1 = fh.y + fl.y;
            s += v0*v0 + v1*v1;
        }
    }
#pragma unroll
    for (int o = 16; o; o >>= 1) s += __shfl_xor_sync(0xffffffffu, s, o);
    if ((t & 31) == 0) red[t >> 5] = s;
    __syncthreads();
    if (t == 0) {
        float tot = red[0] + red[1] + red[2] + red[3];
        atomicMax(&g_maxssq[row / LTOT], __float_as_int(tot));
    }
}

// ---------------- scores GEMM: 512 threads, all-frags-upfront kstep ---------------
__global__ void __launch_bounds__(512, 1) scores_mma() {
    extern __shared__ __align__(1024) char smem[];
    const int t = threadIdx.x, lane = t & 31, wid = t >> 5;
    const int wm = wid >> 2, wn = wid & 3;
    const int ntile = blockIdx.x, mtile = blockIdx.y, n = blockIdx.z;
    const uint32_t sb = smem_u32(smem);

    const __nv_bfloat16* Ab = g_A + (size_t)n*KROW*MTOT + mtile*GM_M;
    const __nv_bfloat16* Bb = g_B + ((size_t)n*LTOT + ntile*GM_N)*KROW;

    float acc[2][6][4];
#pragma unroll
    for (int a = 0; a < 2; a++)
#pragma unroll
        for (int b = 0; b < 6; b++)
#pragma unroll
            for (int c = 0; c < 4; c++) acc[a][b][c] = 0.f;

    auto issue = [&](int kk, int s) {
        uint32_t base = sb + s*S2_STAGE;
        int k0 = kk*64;
#pragma unroll
        for (int e = 0; e < 2; e++) {
            int idx = t + e*512;
            int row = idx >> 4, col = idx & 15;
            uint32_t off = SWZA((uint32_t)row*256 + col*16);
            const __nv_bfloat16* rp = Ab + (size_t)(k0 + row)*MTOT + col*8;
            cp16(base + off, rp);
            cp16(base + S2_ALO + off, rp + (size_t)KHALF*MTOT);
        }
#pragma unroll
        for (int e = 0; e < 3; e++) {
            int idx = t + e*512;
            int row = idx >> 3, col = idx & 7;
            uint32_t off = SWZB((uint32_t)row*128 + col*16);
            const __nv_bfloat16* rp = Bb + (size_t)row*KROW + k0 + col*8;
            cp16(base + S2_BHI + off, rp);
            cp16(base + S2_BLO + off, rp + KHALF);
        }
        asm volatile("cp.async.commit_group;");
    };

    issue(0, 0);
    asm volatile("cp.async.wait_group 0;");
    __syncthreads();

    for (int kk = 0; kk < SCHUNK; kk++) {
        int s = kk & 1;
        if (kk < SCHUNK-1) issue(kk + 1, s ^ 1);
        uint32_t base = sb + s*S2_STAGE;
#pragma unroll
        for (int st = 0; st < 4; st++) {
            int krow  = st*16 + (lane & 7) + ((lane >> 4) & 1)*8;
            int mhalf = (lane >> 3) & 1;
            int kbyte = st*32 + (lane >> 4)*16;
            uint32_t ah[2][4], al[2][4], bh[3][4], bl[3][4];
#pragma unroll
            for (int mi = 0; mi < 2; mi++) {
                uint32_t off = SWZA((uint32_t)krow*256 + (wm*32 + mi*16 + mhalf*8)*2);
                ldsm4t(ah[mi], base + off);
                ldsm4t(al[mi], base + S2_ALO + off);
            }
#pragma unroll
            for (int nj = 0; nj < 3; nj++) {
                uint32_t off = SWZB((uint32_t)(wn*48 + nj*16 + (lane & 15))*128 + kbyte);
                ldsm4(bh[nj], base + S2_BHI + off);
                ldsm4(bl[nj], base + S2_BLO + off);
            }
#pragma unroll
            for (int mi = 0; mi < 2; mi++)
#pragma unroll
                for (int ni = 0; ni < 6; ni++) {
                    int nj = ni >> 1;
                    uint32_t b0h = (ni & 1) ? bh[nj][1] : bh[nj][0];
                    uint32_t b1h = (ni & 1) ? bh[nj][3] : bh[nj][2];
                    uint32_t b0l = (ni & 1) ? bl[nj][1] : bl[nj][0];
                    uint32_t b1l = (ni & 1) ? bl[nj][3] : bl[nj][2];
                    mma_bf16(acc[mi][ni], ah[mi], b0h, b1h);
                    mma_bf16(acc[mi][ni], al[mi], b0h, b1h);
                    mma_bf16(acc[mi][ni], ah[mi], b0l, b1l);
                }
        }
        if (kk < SCHUNK-1) asm volatile("cp.async.wait_group 0;");
        __syncthreads();
    }

    int mbase = mtile*GM_M + wm*32 + (lane >> 2);
    int nbase = ntile*GM_N + wn*48 + (lane & 3)*2;
#pragma unroll
    for (int mi = 0; mi < 2; mi++)
#pragma unroll
        for (int ni = 0; ni < 6; ni++) {
            int m0 = mbase + mi*16;
            int nc = nbase + ni*8;
            float* r0 = g_attn + ((size_t)n*QPOS + m0)*LTOT + nc;
            float* r1 = r0 + 8*LTOT;
            *reinterpret_cast<float2*>(r0) = make_float2(acc[mi][ni][0], acc[mi][ni][1]);
            *reinterpret_cast<float2*>(r1) = make_float2(acc[mi][ni][2], acc[mi][ni][3]);
        }
}

// ---------------- out GEMM with FUSED softmax: A resident in smem ------------------
// CTA: 64 m rows. Prologue: softmax 64 rows from f32 scores -> bf16 hi/lo smem A
// (18 chunks of [64 rows x 128B], swizzled). Then GEMM vs vb with B double-buffer.
__global__ void __launch_bounds__(256, 1) out_mma() {
    extern __shared__ __align__(1024) char smem[];
    const int t = threadIdx.x, lane = t & 31, wid = t >> 5;
    const int wm = wid >> 2, wn = wid & 3;
    const int mtile = blockIdx.x, n = blockIdx.z;
    const uint32_t sbA = smem_u32(smem);
    const uint32_t sbB = sbA + OM_B;

    // ---- fused softmax prologue: warp w handles rows w*8 .. w*8+7
    {
        float scale = 10.f / sqrtf(__int_as_float(g_maxssq[n]));
#pragma unroll 1
        for (int rr = 0; rr < 8; rr++) {
            int row = wid*8 + rr;
            const float* rp = g_attn + ((size_t)n*QPOS + mtile*G2_M + row)*LTOT;
            float v[18];
            float m = -1e30f;
#pragma unroll
            for (int j = 0; j < 18; j++) {
                v[j] = rp[lane + 32*j] * scale;
                m = fmaxf(m, v[j]);
            }
#pragma unroll
            for (int o = 16; o; o >>= 1) m = fmaxf(m, __shfl_xor_sync(0xffffffffu, m, o));
            float s = 0.f;
#pragma unroll
            for (int j = 0; j < 18; j++) { v[j] = __expf(v[j] - m); s += v[j]; }
#pragma unroll
            for (int o = 16; o; o >>= 1) s += __shfl_xor_sync(0xffffffffu, s, o);
            float inv = 1.f / s;
#pragma unroll
            for (int j = 0; j < 18; j++) {
                float val = v[j] * inv;
                __nv_bfloat16 h = __float2bfloat16(val);
                __nv_bfloat16 l = __float2bfloat16(val - __bfloat162float(h));
                int k = lane + 32*j;
                uint32_t off = SWZB((uint32_t)row*128 + (k & 63)*2);
                uint32_t cb = sbA + (uint32_t)(k >> 6)*8192;
                sts16(cb + off, __bfloat16_as_ushort(h));
                sts16(cb + 9*8192 + off, __bfloat16_as_ushort(l));
            }
        }
    }

    const __nv_bfloat16* Bbase = g_vb + (size_t)n*G2_N*AK;

    float acc[2][8][4];
#pragma unroll
    for (int a = 0; a < 2; a++)
#pragma unroll
        for (int b = 0; b < 8; b++)
#pragma unroll
            for (int c = 0; c < 4; c++) acc[a][b][c] = 0.f;

    auto issueB = [&](int kk, int s) {
        int kb;
        if (kk < 9)       kb = kk*64;
        else if (kk < 18) kb = (kk-9)*64;
        else              kb = LTOT + (kk-18)*64;
        uint32_t Bs = sbB + s*OM_BSTAGE;
#pragma unroll
        for (int e = 0; e < 8; e++) {
            int idx = t + e*256;
            int row = idx >> 3, col = idx & 7;
            uint32_t off = (uint32_t)row*128 + col*16;
            cp16(Bs + SWZB(off), Bbase + (size_t)row*AK + kb + col*8);
        }
        asm volatile("cp.async.commit_group;");
    };

    issueB(0, 0);
    asm volatile("cp.async.wait_group 0;");
    __syncthreads();     // covers softmax staging + B chunk 0

    for (int kk = 0; kk < G2_NCHUNK; kk++) {
        int s = kk & 1;
        if (kk < G2_NCHUNK-1) issueB(kk + 1, s ^ 1);

        // A chunk: hi 0..8 for regions 0 and 2, lo 9..17 for region 1
        int ach;
        if (kk < 9)       ach = kk;
        else if (kk < 18) ach = kk;        // 9..17 = lo chunks
        else              ach = kk - 18;
        uint32_t As = sbA + (uint32_t)ach*8192;
        uint32_t Bs = sbB + s*OM_BSTAGE;
#pragma unroll
        for (int st = 0; st < 4; st++) {
            int kbyte = st*32 + (lane >> 4)*16;
            uint32_t a[2][4];
#pragma unroll
            for (int mi = 0; mi < 2; mi++) {
                uint32_t off = (uint32_t)(wm*32 + mi*16 + (lane & 15))*128 + kbyte;
                ldsm4(a[mi], As + SWZB(off));
            }
            uint32_t b[4][4];
#pragma unroll
            for (int nj = 0; nj < 4; nj++) {
                uint32_t off = (uint32_t)(wn*64 + nj*16 + (lane & 15))*128 + kbyte;
                ldsm4(b[nj], Bs + SWZB(off));
            }
#pragma unroll
            for (int mi = 0; mi < 2; mi++)
#pragma unroll
                for (int ni = 0; ni < 8; ni++) {
                    int nj = ni >> 1;
                    if (ni & 1) mma_bf16(acc[mi][ni], a[mi], b[nj][1], b[nj][3]);
                    else        mma_bf16(acc[mi][ni], a[mi], b[nj][0], b[nj][2]);
                }
        }
        if (kk < G2_NCHUNK-1) asm volatile("cp.async.wait_group 0;");
        __syncthreads();
    }

    int mbase = mtile*G2_M + wm*32 + (lane >> 2);
    int nbase = wn*64 + (lane & 3)*2;
#pragma unroll
    for (int mi = 0; mi < 2; mi++)
#pragma unroll
        for (int ni = 0; ni < 8; ni++) {
            int m0 = mbase + mi*16;
            int nc = nbase + ni*8;
            float* r0 = g_out2 + ((size_t)n*QPOS + m0)*G2_N + nc;
            float* r1 = r0 + 8*G2_N;
            *reinterpret_cast<float2*>(r0) = make_float2(acc[mi][ni][0], acc[mi][ni][1]);
            *reinterpret_cast<float2*>(r1) = make_float2(acc[mi][ni][2], acc[mi][ni][3]);
        }
}

// ---------------- fused scatter + final 3x3 conv -> d_out --------------------------
__global__ void scatter_conv(const float* __restrict__ wr, const float* __restrict__ br,
                             float* __restrict__ out) {
    __shared__ float sres[BAND][10][34];
    __shared__ float swr[9*BAND][BAND];
    __shared__ float sbr[BAND];
    int t = threadIdx.x;
    int bx = blockIdx.x, by = blockIdx.y, n = blockIdx.z;

    for (int e = t; e < BAND*BAND*9; e += 256) {
        int co = e / (BAND*9), rem = e % (BAND*9);
        swr[rem][co] = wr[e];
    }
    if (t < BAND) sbr[t] = br[t];

    int yh0 = by*8 - 1, xh0 = bx*32 - 1;
    const float* base = g_out2 + (size_t)n*QPOS*G2_N;
    for (int e = t; e < 10*34; e += 256) {
        int ry = e / 34, rx = e % 34;
        int y = yh0 + ry, x = xh0 + rx;
        float acc[BAND];
#pragma unroll
        for (int b = 0; b < BAND; b++) acc[b] = 0.f;
        if (y >= 0 && y < HQP && x >= 0 && x < HQP) {
            int oyA = y >> 2, iA = y & 3;  bool vA = oyA < QW;
            int oyB = oyA - 1;             bool vB = (iA == 0) && (oyB >= 0);
            int oxA = x >> 2, jA = x & 3;  bool hA = oxA < QW;
            int oxB = oxA - 1;             bool hB = (jA == 0) && (oxB >= 0);
#pragma unroll
            for (int ti = 0; ti < 2; ti++) {
                bool vi = ti ? vB : vA;
                if (!vi) continue;
                int oy = ti ? oyB : oyA;
                int ii = ti ? 4 : iA;
#pragma unroll
                for (int tj = 0; tj < 2; tj++) {
                    bool vj = tj ? hB : hA;
                    if (!vj) continue;
                    int ox = tj ? oxB : oxA;
                    int jj = tj ? 4 : jA;
                    const float* row = base + (size_t)(oy*QW + ox)*G2_N + ii*5 + jj;
#pragma unroll
                    for (int b = 0; b < BAND; b++) acc[b] += __ldg(&row[b*PP]);
                }
            }
        }
#pragma unroll
        for (int b = 0; b < BAND; b++) sres[b][ry][rx] = acc[b] * (1.f/6.f);
    }
    __syncthreads();

    int ly = t >> 5, lx = t & 31;
    int y = by*8 + ly, x = bx*32 + lx;
    if (y >= HQP || x >= HQP) return;
    float acc[BAND];
#pragma unroll
    for (int co = 0; co < BAND; co++) acc[co] = sbr[co];
#pragma unroll
    for (int ci = 0; ci < BAND; ci++)
#pragma unroll
        for (int dy = 0; dy < 3; dy++)
#pragma unroll
            for (int dx = 0; dx < 3; dx++) {
                float v = sres[ci][ly + dy][lx + dx];
                const float* wp = &swr[(ci*9 + dy*3 + dx)][0];
#pragma unroll
                for (int co = 0; co < BAND; co++) acc[co] += v * wp[co];
            }
#pragma unroll
    for (int co = 0; co < BAND; co++)
        out[(((size_t)n*BAND + co)*HQP + y)*HQP + x] = lrelu(acc[co]);
}

// ---------------- launch -----------------------------------------------------------
extern "C" void kernel_launch(void* const* d_in, const int* in_sizes, int n_in,
                              void* d_out, int out_size) {
    const float* ms   = (const float*)d_in[0];
    const float* pan  = (const float*)d_in[1];
    const float* pan2 = (const float*)d_in[2];
    const float* wq = (const float*)d_in[3];
    const float* bq = (const float*)d_in[4];
    const float* wk = (const float*)d_in[5];
    const float* bk = (const float*)d_in[6];
    const float* wv = (const float*)d_in[7];
    const float* bv = (const float*)d_in[8];
    const float* wr = (const float*)d_in[9];
    const float* br = (const float*)d_in[10];
    float* out = (float*)d_out;

    void* pv;
    cudaGetSymbolAddress(&pv, g_kfea); float* kfea = (float*)pv;

    cudaFuncSetAttribute(scores_mma, cudaFuncAttributeMaxDynamicSharedMemorySize, S2_TOTAL);
    cudaFuncSetAttribute(out_mma,    cudaFuncAttributeMaxDynamicSharedMemorySize, OM_TOTAL);

    // 1-3: k features, fused keys-bf16 + q-conv + A im2col, v patches
    conv_1toC<MID, HS, HS><<<dim3((HS*HS + 255)/256, NB), 256>>>(pan2, wk, bk, kfea);
    prep_kernel<<<NB*MID + NB*16*QW, 512>>>(pan, wq, bq);
    gather_v_fused<<<NB*BAND*PP, LTOT>>>(ms, wv, bv);

    // 4: the big one (profiled slot)
    scores_mma<<<dim3(LTOT/GM_N, MTOT/GM_M, NB), 512, S2_TOTAL>>>();

    // norm scale + fused softmax/out-GEMM + fused scatter/conv
    ssq_b<<<NB*LTOT, 128>>>();
    out_mma<<<dim3(QPOS/G2_M, 1, NB), 256, OM_TOTAL>>>();
    scatter_conv<<<dim3(13, 49, NB), 256>>>(wr, br, out);
}

// round 16
// speedup vs baseline: 1.0751x; 1.0751x over previous
#include <cuda_runtime.h>
#include <cuda_bf16.h>
#include <cstdint>

#define NB 2
#define MID 64
#define BAND 8
#define HS 96
#define HQ 384
#define HQP 385
#define LTOT 576
#define PP 25
#define QW 96
#define QPOS (QW*QW)

// scores GEMM tiling (fused im2col A, 384 threads, k64 chunks)
#define GM_M 96
#define GM_N 192
#define KHALF 1600
#define KROW 3200
#define SCHUNK 25
#define SC_AHI 0
#define SC_ALO 12288
#define SC_BHI 24576
#define SC_BLO 49152
#define SC_STAGE 73728
#define SC_TOTAL (2*SC_STAGE)

// out GEMM (attn x v) tiling
#define G2_M 64
#define G2_N 256
#define AK 1152
#define G2_NCHUNK 27
#define G2_SMA 8192
#define G2_SMB 32768
#define G2_STAGE (G2_SMA + G2_SMB)
#define G2_TOTAL (2*G2_STAGE)

// ---------------- scratch (device globals; no runtime allocation) ------------
__device__ float g_kfea[NB*MID*HS*HS];
__device__ float g_qfea[NB*MID*HQP*HQP];      // padded (row/col 384 = 0)
__device__ int   g_maxssq[NB];
__device__ float g_attn[NB*QPOS*LTOT];        // f32 scores (pre-softmax)
__device__ __nv_bfloat16 g_B[(size_t)NB*LTOT*KROW];   // keys [n][l][hi1600|lo1600]
__device__ __nv_bfloat16 g_attnb[(size_t)NB*QPOS*AK]; // softmaxed attn bf16 hi|lo
__device__ __nv_bfloat16 g_vb[(size_t)NB*G2_N*AK];    // [n][b*25+p][hi|lo]
__device__ float g_out2[(size_t)NB*QPOS*G2_N];

__device__ __forceinline__ float lrelu(float v) { return v > 0.f ? v : 0.01f * v; }

__device__ __forceinline__ uint32_t smem_u32(const void* p) {
    uint32_t a;
    asm("{ .reg .u64 t; cvta.to.shared.u64 t, %1; cvt.u32.u64 %0, t; }" : "=r"(a) : "l"(p));
    return a;
}
__device__ __forceinline__ void cp16(uint32_t dst, const void* src) {
    asm volatile("cp.async.cg.shared.global [%0], [%1], 16;" :: "r"(dst), "l"(src));
}
__device__ __forceinline__ void ldsm4(uint32_t* r, uint32_t a) {
    asm volatile("ldmatrix.sync.aligned.m8n8.x4.shared.b16 {%0,%1,%2,%3}, [%4];"
                 : "=r"(r[0]), "=r"(r[1]), "=r"(r[2]), "=r"(r[3]) : "r"(a));
}
__device__ __forceinline__ void mma_bf16(float* c, const uint32_t* a, uint32_t b0, uint32_t b1) {
    asm volatile("mma.sync.aligned.m16n8k16.row.col.f32.bf16.bf16.f32 "
                 "{%0,%1,%2,%3}, {%4,%5,%6,%7}, {%8,%9}, {%0,%1,%2,%3};"
                 : "+f"(c[0]), "+f"(c[1]), "+f"(c[2]), "+f"(c[3])
                 : "r"(a[0]), "r"(a[1]), "r"(a[2]), "r"(a[3]), "r"(b0), "r"(b1));
}
#define SWZB(o) ((o) ^ (((o) >> 3) & 0x70))   // 128B rows

// ---------------- 3x3 conv, 1 -> C channels -----------------------------------
template<int C, int HIN, int HOUT>
__global__ void conv_1toC(const float* __restrict__ in, const float* __restrict__ w,
                          const float* __restrict__ bias, float* __restrict__ out) {
    __shared__ float sw[C*9];
    __shared__ float sb[C];
    int t = threadIdx.x;
    for (int e = t; e < C*9; e += blockDim.x) sw[e] = w[e];
    for (int e = t; e < C;   e += blockDim.x) sb[e] = bias[e];
    __syncthreads();
    int idx = blockIdx.x * blockDim.x + t;
    int n = blockIdx.y;
    if (idx >= HOUT*HOUT) return;
    int y = idx / HOUT, x = idx % HOUT;
    bool inside = (y < HIN) && (x < HIN);
    float v[9];
#pragma unroll
    for (int dy = 0; dy < 3; dy++)
#pragma unroll
        for (int dx = 0; dx < 3; dx++) {
            int yy = y + dy - 1, xx = x + dx - 1;
            v[dy*3+dx] = (inside && yy >= 0 && yy < HIN && xx >= 0 && xx < HIN)
                         ? in[(n*HIN + yy)*HIN + xx] : 0.f;
        }
#pragma unroll 8
    for (int c = 0; c < C; c++) {
        float s = 0.f;
        if (inside) {
            s = sb[c];
#pragma unroll
            for (int k = 0; k < 9; k++) s += v[k] * sw[c*9 + k];
            s = lrelu(s);
        }
        out[((n*C + c)*HOUT + y)*HOUT + x] = s;
    }
}

// ---------------- K patches -> bf16 hi/lo B matrix -------------------------------
__global__ void build_b_direct() {
    if (blockIdx.x == 0 && threadIdx.x < NB) g_maxssq[threadIdx.x] = 0;
    int n = blockIdx.x >> 6, c = blockIdx.x & 63;
    int l = threadIdx.x;                  // 576
    int py = l / 24, px = l % 24;
    __nv_bfloat16* dst = g_B + ((size_t)(n*LTOT) + l)*KROW + c*PP;
    const float* src = g_kfea + ((size_t)(n*MID + c))*HS*HS;
#pragma unroll
    for (int p = 0; p < PP; p++) {
        int i = p / 5, j = p % 5;
        int sy = 4*py + i - 2; if (sy < 0) sy += 97;
        int sx = 4*px + j - 2; if (sx < 0) sx += 97;
        float v = 0.f;
        if (sy < HS && sx < HS) v = src[sy*HS + sx];
        __nv_bfloat16 h = __float2bfloat16(v);
        dst[p] = h;
        dst[KHALF + p] = __float2bfloat16(v - __bfloat162float(h));
    }
}

// ---------------- V: fused 3x3 conv + patch gather -> bf16 hi/lo ----------------
__global__ void gather_v_fused(const float* __restrict__ ms,
                               const float* __restrict__ wv,
                               const float* __restrict__ bv) {
    __shared__ float sw[BAND*9];
    __shared__ float sbv;
    int bid = blockIdx.x;                 // n*200 + b*25 + p
    int n  = bid / (BAND*PP);
    int bp = bid % (BAND*PP);
    int b  = bp / PP;
    int p  = bp % PP;
    int i  = p / 5, j = p % 5;
    int l  = threadIdx.x;
    if (l < BAND*9) sw[l] = wv[b*BAND*9 + l];
    if (l == BAND*9) sbv = bv[b];
    __syncthreads();

    int py = l / 24, px = l % 24;
    int sy = 4*py + i - 2; if (sy < 0) sy += 97;
    int sx = 4*px + j - 2; if (sx < 0) sx += 97;
    float v = 0.f;
    if (sy < HS && sx < HS) {
        float s = sbv;
        const float* mn = ms + (size_t)n*BAND*HS*HS;
#pragma unroll
        for (int ci = 0; ci < BAND; ci++) {
            const float* ip = mn + (size_t)ci*HS*HS;
#pragma unroll
            for (int dy = 0; dy < 3; dy++) {
                int yy = sy + dy - 1;
                if (yy < 0 || yy >= HS) continue;
#pragma unroll
                for (int dx = 0; dx < 3; dx++) {
                    int xx = sx + dx - 1;
                    if (xx < 0 || xx >= HS) continue;
                    s += __ldg(&ip[yy*HS + xx]) * sw[ci*9 + dy*3 + dx];
                }
            }
        }
        v = lrelu(s);
    }
    __nv_bfloat16 h = __float2bfloat16(v);
    __nv_bfloat16* dst = g_vb + ((size_t)(n*G2_N) + bp)*AK;
    dst[l] = h;
    dst[LTOT + l] = __float2bfloat16(v - __bfloat162float(h));
}

// ---------------- per-patch ssq from g_B (hi+lo) + atomic max ---------------------
__global__ void ssq_b() {
    __shared__ float red[4];
    int row = blockIdx.x;
    int t = threadIdx.x;
    const uint4* rp = reinterpret_cast<const uint4*>(g_B + (size_t)row*KROW);
    float s = 0.f;
    for (int e = t; e < 200; e += 128) {
        uint4 hi = __ldg(&rp[e]);
        uint4 lo = __ldg(&rp[200 + e]);
        const uint32_t* hw = &hi.x;
        const uint32_t* lw = &lo.x;
#pragma unroll
        for (int q = 0; q < 4; q++) {
            float2 fh = __bfloat1622float2(*reinterpret_cast<const __nv_bfloat162*>(&hw[q]));
            float2 fl = __bfloat1622float2(*reinterpret_cast<const __nv_bfloat162*>(&lw[q]));
            float v0 = fh.x + fl.x, v1 = fh.y + fl.y;
            s += v0*v0 + v1*v1;
        }
    }
#pragma unroll
    for (int o = 16; o; o >>= 1) s += __shfl_xor_sync(0xffffffffu, s, o);
    if ((t & 31) == 0) red[t >> 5] = s;
    __syncthreads();
    if (t == 0) {
        float tot = red[0] + red[1] + red[2] + red[3];
        atomicMax(&g_maxssq[row / LTOT], __float_as_int(tot));
    }
}

// ---------------- scores GEMM: fused im2col A, 384 thr (12 warps 2m x 6n) ---------
// CTA: oy row (96 queries) x 192 keys. Warp tile 48m x 32n. k64 double-buffered.
__global__ void __launch_bounds__(384, 1) scores_mma() {
    extern __shared__ __align__(1024) char smem[];
    __shared__ int offs[KHALF];
    const int t = threadIdx.x, lane = t & 31, wid = t >> 5;
    const int wm = wid / 6, wn = wid % 6;
    const int ntile = blockIdx.x, oy = blockIdx.y, n = blockIdx.z;
    const uint32_t sb = smem_u32(smem);

    const float* Qn = g_qfea + (size_t)n*MID*HQP*HQP + (4*oy)*HQP;
    const __nv_bfloat16* Bb = g_B + ((size_t)n*LTOT + ntile*GM_N)*KROW;

    for (int e = t; e < KHALF; e += 384) {
        int c = e / 25, p = e % 25, i = p / 5, j = p % 5;
        offs[e] = (c*HQP + i)*HQP + j;
    }

    float acc[3][4][4];
#pragma unroll
    for (int a = 0; a < 3; a++)
#pragma unroll
        for (int b = 0; b < 4; b++)
#pragma unroll
            for (int c = 0; c < 4; c++) acc[a][b][c] = 0.f;

    float pv0[4], pv1[4];

    auto prefA = [&](int kk, int half) {
#pragma unroll
        for (int it = 0; it < 4; it++) {
            int idx = (half*4 + it)*384 + t;
            int m = idx >> 5, kp = idx & 31;
            int k = kk*64 + kp*2;
            pv0[it] = __ldg(&Qn[offs[k]   + 4*m]);
            pv1[it] = __ldg(&Qn[offs[k+1] + 4*m]);
        }
    };
    auto storeA = [&](int s, int half) {
        char* base = smem + s*SC_STAGE;
#pragma unroll
        for (int it = 0; it < 4; it++) {
            int idx = (half*4 + it)*384 + t;
            int m = idx >> 5, kp = idx & 31;
            float v0 = pv0[it], v1 = pv1[it];
            __nv_bfloat16 h0 = __float2bfloat16(v0);
            __nv_bfloat16 h1 = __float2bfloat16(v1);
            __nv_bfloat16 l0 = __float2bfloat16(v0 - __bfloat162float(h0));
            __nv_bfloat16 l1 = __float2bfloat16(v1 - __bfloat162float(h1));
            uint32_t hp = (uint32_t)__bfloat16_as_ushort(h0) |
                          ((uint32_t)__bfloat16_as_ushort(h1) << 16);
            uint32_t lp = (uint32_t)__bfloat16_as_ushort(l0) |
                          ((uint32_t)__bfloat16_as_ushort(l1) << 16);
            uint32_t sw = SWZB((uint32_t)m*128 + kp*4);
            *reinterpret_cast<uint32_t*>(base + SC_AHI + sw) = hp;
            *reinterpret_cast<uint32_t*>(base + SC_ALO + sw) = lp;
        }
    };
    auto issueB = [&](int kk, int s) {
        uint32_t bhi = sb + s*SC_STAGE + SC_BHI;
        uint32_t blo = sb + s*SC_STAGE + SC_BLO;
        int k0 = kk*64;
#pragma unroll
        for (int e = 0; e < 4; e++) {
            int idx = t + e*384;
            int row = idx >> 3, col = idx & 7;
            uint32_t off = SWZB((uint32_t)row*128 + col*16);
            const __nv_bfloat16* rp = Bb + (size_t)row*KROW + k0 + col*8;
            cp16(bhi + off, rp);
            cp16(blo + off, rp + KHALF);
        }
        asm volatile("cp.async.commit_group;");
    };

    // one k16-step: all fragments loaded upfront, then 36 MMAs
    auto kstep = [&](int s, int st) {
        uint32_t base = sb + s*SC_STAGE;
        uint32_t col = (uint32_t)(st*32 + (lane >> 4)*16);
        uint32_t ah[3][4], al[3][4], bh[2][4], bl[2][4];
#pragma unroll
        for (int mi = 0; mi < 3; mi++) {
            uint32_t row = wm*48 + mi*16 + (lane & 15);
            uint32_t sw = SWZB(row*128 + col);
            ldsm4(ah[mi], base + SC_AHI + sw);
            ldsm4(al[mi], base + SC_ALO + sw);
        }
#pragma unroll
        for (int nj = 0; nj < 2; nj++) {
            uint32_t row = wn*32 + nj*16 + (lane & 15);
            uint32_t sw = SWZB(row*128 + col);
            ldsm4(bh[nj], base + SC_BHI + sw);
            ldsm4(bl[nj], base + SC_BLO + sw);
        }
#pragma unroll
        for (int mi = 0; mi < 3; mi++)
#pragma unroll
            for (int ni = 0; ni < 4; ni++) {
                int nj = ni >> 1;
                uint32_t b0h = (ni & 1) ? bh[nj][1] : bh[nj][0];
                uint32_t b1h = (ni & 1) ? bh[nj][3] : bh[nj][2];
                uint32_t b0l = (ni & 1) ? bl[nj][1] : bl[nj][0];
                uint32_t b1l = (ni & 1) ? bl[nj][3] : bl[nj][2];
                mma_bf16(acc[mi][ni], ah[mi], b0h, b1h);
                mma_bf16(acc[mi][ni], al[mi], b0h, b1h);
                mma_bf16(acc[mi][ni], ah[mi], b0l, b1l);
            }
    };

    // prologue: stage chunk 0 fully
    issueB(0, 0);
    prefA(0, 0); storeA(0, 0);
    prefA(0, 1); storeA(0, 1);
    asm volatile("cp.async.wait_group 0;");
    __syncthreads();

    for (int kk = 0; kk < SCHUNK; kk++) {
        int s = kk & 1;
        bool more = (kk < SCHUNK-1);
        if (more) { issueB(kk + 1, s ^ 1); prefA(kk + 1, 0); }
        kstep(s, 0);
        kstep(s, 1);
        if (more) { storeA(s ^ 1, 0); prefA(kk + 1, 1); }
        kstep(s, 2);
        kstep(s, 3);
        if (more) {
            storeA(s ^ 1, 1);
            asm volatile("cp.async.wait_group 0;");
        }
        __syncthreads();
    }

    // epilogue: f32 scores
    int mbase = oy*QW + wm*48 + (lane >> 2);
    int nbase = ntile*GM_N + wn*32 + (lane & 3)*2;
#pragma unroll
    for (int mi = 0; mi < 3; mi++)
#pragma unroll
        for (int ni = 0; ni < 4; ni++) {
            int m0 = mbase + mi*16;
            int nc = nbase + ni*8;
            float* r0 = g_attn + ((size_t)n*QPOS + m0)*LTOT + nc;
            float* r1 = r0 + 8*LTOT;
            *reinterpret_cast<float2*>(r0) = make_float2(acc[mi][ni][0], acc[mi][ni][1]);
            *reinterpret_cast<float2*>(r1) = make_float2(acc[mi][ni][2], acc[mi][ni][3]);
        }
}

// ---------------- softmax over 576 keys -> bf16 hi/lo attn -------------------------
__global__ void softmax_kernel() {
    int w    = threadIdx.x >> 5;
    int lane = threadIdx.x & 31;
    int gw = blockIdx.x * 8 + w;
    int n = gw / QPOS;
    float scale = 10.f / sqrtf(__int_as_float(g_maxssq[n]));
    const float* row = g_attn + (size_t)gw * LTOT;
    __nv_bfloat16* rowb = g_attnb + (size_t)gw * AK;
    float v[18];
    float m = -1e30f;
#pragma unroll
    for (int k = 0; k < 18; k++) {
        v[k] = row[lane + 32*k] * scale;
        m = fmaxf(m, v[k]);
    }
#pragma unroll
    for (int o = 16; o; o >>= 1) m = fmaxf(m, __shfl_xor_sync(0xffffffffu, m, o));
    float s = 0.f;
#pragma unroll
    for (int k = 0; k < 18; k++) { v[k] = __expf(v[k] - m); s += v[k]; }
#pragma unroll
    for (int o = 16; o; o >>= 1) s += __shfl_xor_sync(0xffffffffu, s, o);
    float inv = 1.f / s;
#pragma unroll
    for (int k = 0; k < 18; k++) {
        float val = v[k] * inv;
        __nv_bfloat16 h = __float2bfloat16(val);
        rowb[lane + 32*k] = h;
        rowb[LTOT + lane + 32*k] = __float2bfloat16(val - __bfloat162float(h));
    }
}

// ---------------- out GEMM: out2[m][200] = attn[m][:] x vb^T, 144 CTAs -------------
__global__ void __launch_bounds__(256, 2) out_mma() {
    extern __shared__ __align__(1024) char smem[];
    const int t = threadIdx.x, lane = t & 31, wid = t >> 5;
    const int wm = wid >> 2, wn = wid & 3;
    const int mtile = blockIdx.x, n = blockIdx.z;
    const uint32_t sb = smem_u32(smem);

    const __nv_bfloat16* Abase = g_attnb + ((size_t)n*QPOS + mtile*G2_M)*AK;
    const __nv_bfloat16* Bbase = g_vb + (size_t)n*G2_N*AK;

    float acc[2][8][4];
#pragma unroll
    for (int a = 0; a < 2; a++)
#pragma unroll
        for (int b = 0; b < 8; b++)
#pragma unroll
            for (int c = 0; c < 4; c++) acc[a][b][c] = 0.f;

    auto issue_chunk = [&](int kk, int s) {
        int ka, kb;
        if (kk < 9)       { ka = kk*64;                kb = kk*64; }
        else if (kk < 18) { ka = LTOT + (kk-9)*64;     kb = (kk-9)*64; }
        else              { ka = (kk-18)*64;           kb = LTOT + (kk-18)*64; }
        uint32_t As = sb + s*G2_STAGE;
        uint32_t Bs = As + G2_SMA;
#pragma unroll
        for (int e = 0; e < 2; e++) {
            int idx = t + e*256;
            int row = idx >> 3, col = idx & 7;
            uint32_t off = (uint32_t)row*128 + col*16;
            cp16(As + SWZB(off), Abase + (size_t)row*AK + ka + col*8);
        }
#pragma unroll
        for (int e = 0; e < 8; e++) {
            int idx = t + e*256;
            int row = idx >> 3, col = idx & 7;
            uint32_t off = (uint32_t)row*128 + col*16;
            cp16(Bs + SWZB(off), Bbase + (size_t)row*AK + kb + col*8);
        }
        asm volatile("cp.async.commit_group;");
    };

    issue_chunk(0, 0);
    asm volatile("cp.async.wait_group 0;");
    __syncthreads();

    for (int kk = 0; kk < G2_NCHUNK; kk++) {
        int s = kk & 1;
        if (kk < G2_NCHUNK-1) issue_chunk(kk + 1, s ^ 1);

        uint32_t As = sb + s*G2_STAGE;
        uint32_t Bs = As + G2_SMA;
#pragma unroll
        for (int st = 0; st < 4; st++) {
            int kbyte = st*32 + (lane >> 4)*16;
            uint32_t a[2][4];
#pragma unroll
            for (int mi = 0; mi < 2; mi++) {
                uint32_t off = (uint32_t)(wm*32 + mi*16 + (lane & 15))*128 + kbyte;
                ldsm4(a[mi], As + SWZB(off));
            }
            uint32_t b[4][4];
#pragma unroll
            for (int nj = 0; nj < 4; nj++) {
                uint32_t off = (uint32_t)(wn*64 + nj*16 + (lane & 15))*128 + kbyte;
                ldsm4(b[nj], Bs + SWZB(off));
            }
#pragma unroll
            for (int mi = 0; mi < 2; mi++)
#pragma unroll
                for (int ni = 0; ni < 8; ni++) {
                    int nj = ni >> 1;
                    if (ni & 1) mma_bf16(acc[mi][ni], a[mi], b[nj][1], b[nj][3]);
                    else        mma_bf16(acc[mi][ni], a[mi], b[nj][0], b[nj][2]);
                }
        }
        if (kk < G2_NCHUNK-1) asm volatile("cp.async.wait_group 0;");
        __syncthreads();
    }

    int mbase = mtile*G2_M + wm*32 + (lane >> 2);
    int nbase = wn*64 + (lane & 3)*2;
#pragma unroll
    for (int mi = 0; mi < 2; mi++)
#pragma unroll
        for (int ni = 0; ni < 8; ni++) {
            int m0 = mbase + mi*16;
            int nc = nbase + ni*8;
            float* r0 = g_out2 + ((size_t)n*QPOS + m0)*G2_N + nc;
            float* r1 = r0 + 8*G2_N;
            *reinterpret_cast<float2*>(r0) = make_float2(acc[mi][ni][0], acc[mi][ni][1]);
            *reinterpret_cast<float2*>(r1) = make_float2(acc[mi][ni][2], acc[mi][ni][3]);
        }
}

// ---------------- fused scatter + final 3x3 conv -> d_out --------------------------
__global__ void scatter_conv(const float* __restrict__ wr, const float* __restrict__ br,
                             float* __restrict__ out) {
    __shared__ float sres[BAND][10][34];
    __shared__ float swr[9*BAND][BAND];
    __shared__ float sbr[BAND];
    int t = threadIdx.x;
    int bx = blockIdx.x, by = blockIdx.y, n = blockIdx.z;

    for (int e = t; e < BAND*BAND*9; e += 256) {
        int co = e / (BAND*9), rem = e % (BAND*9);
        swr[rem][co] = wr[e];
    }
    if (t < BAND) sbr[t] = br[t];

    int yh0 = by*8 - 1, xh0 = bx*32 - 1;
    const float* base = g_out2 + (size_t)n*QPOS*G2_N;
    for (int e = t; e < 10*34; e += 256) {
        int ry = e / 34, rx = e % 34;
        int y = yh0 + ry, x = xh0 + rx;
        float acc[BAND];
#pragma unroll
        for (int b = 0; b < BAND; b++) acc[b] = 0.f;
        if (y >= 0 && y < HQP && x >= 0 && x < HQP) {
            int oyA = y >> 2, iA = y & 3;  bool vA = oyA < QW;
            int oyB = oyA - 1;             bool vB = (iA == 0) && (oyB >= 0);
            int oxA = x >> 2, jA = x & 3;  bool hA = oxA < QW;
            int oxB = oxA - 1;             bool hB = (jA == 0) && (oxB >= 0);
#pragma unroll
            for (int ti = 0; ti < 2; ti++) {
                bool vi = ti ? vB : vA;
                if (!vi) continue;
                int oy = ti ? oyB : oyA;
                int ii = ti ? 4 : iA;
#pragma unroll
                for (int tj = 0; tj < 2; tj++) {
                    bool vj = tj ? hB : hA;
                    if (!vj) continue;
                    int ox = tj ? oxB : oxA;
                    int jj = tj ? 4 : jA;
                    const float* row = base + (size_t)(oy*QW + ox)*G2_N + ii*5 + jj;
#pragma unroll
                    for (int b = 0; b < BAND; b++) acc[b] += __ldg(&row[b*PP]);
                }
            }
        }
#pragma unroll
        for (int b = 0; b < BAND; b++) sres[b][ry][rx] = acc[b] * (1.f/6.f);
    }
    __syncthreads();

    int ly = t >> 5, lx = t & 31;
    int y = by*8 + ly, x = bx*32 + lx;
    if (y >= HQP || x >= HQP) return;
    float acc[BAND];
#pragma unroll
    for (int co = 0; co < BAND; co++) acc[co] = sbr[co];
#pragma unroll
    for (int ci = 0; ci < BAND; ci++)
#pragma unroll
        for (int dy = 0; dy < 3; dy++)
#pragma unroll
            for (int dx = 0; dx < 3; dx++) {
                float v = sres[ci][ly + dy][lx + dx];
                const float* wp = &swr[(ci*9 + dy*3 + dx)][0];
#pragma unroll
                for (int co = 0; co < BAND; co++) acc[co] += v * wp[co];
            }
#pragma unroll
    for (int co = 0; co < BAND; co++)
        out[(((size_t)n*BAND + co)*HQP + y)*HQP + x] = lrelu(acc[co]);
}

// ---------------- launch -----------------------------------------------------------
extern "C" void kernel_launch(void* const* d_in, const int* in_sizes, int n_in,
                              void* d_out, int out_size) {
    const float* ms   = (const float*)d_in[0];
    const float* pan  = (const float*)d_in[1];
    const float* pan2 = (const float*)d_in[2];
    const float* wq = (const float*)d_in[3];
    const float* bq = (const float*)d_in[4];
    const float* wk = (const float*)d_in[5];
    const float* bk = (const float*)d_in[6];
    const float* wv = (const float*)d_in[7];
    const float* bv = (const float*)d_in[8];
    const float* wr = (const float*)d_in[9];
    const float* br = (const float*)d_in[10];
    float* out = (float*)d_out;

    void* pv;
    cudaGetSymbolAddress(&pv, g_kfea); float* kfea = (float*)pv;
    cudaGetSymbolAddress(&pv, g_qfea); float* qfea = (float*)pv;

    cudaFuncSetAttribute(scores_mma, cudaFuncAttributeMaxDynamicSharedMemorySize, SC_TOTAL);
    cudaFuncSetAttribute(out_mma,    cudaFuncAttributeMaxDynamicSharedMemorySize, G2_TOTAL);

    // 1-3: q features (padded), k features, keys bf16
    conv_1toC<MID, HQ, HQP> <<<dim3((HQP*HQP + 255)/256, NB), 256>>>(pan,  wq, bq, qfea);
    conv_1toC<MID, HS, HS>  <<<dim3((HS*HS   + 255)/256, NB), 256>>>(pan2, wk, bk, kfea);
    build_b_direct<<<NB*MID, LTOT>>>();

    // 4: the big one (profiled slot) — fused-A, no g_A roundtrip
    scores_mma<<<dim3(LTOT/GM_N, QW, NB), 384, SC_TOTAL>>>();

    // v patches (fused conv), norm scale
    gather_v_fused<<<NB*BAND*PP, LTOT>>>(ms, wv, bv);
    ssq_b<<<NB*LTOT, 128>>>();

    // softmax + output GEMM + fused scatter/conv
    softmax_kernel<<<NB*QPOS/8, 256>>>();
    out_mma<<<dim3(QPOS/G2_M, 1, NB), 256, G2_TOTAL>>>();
    scatter_conv<<<dim3(13, 49, NB), 256>>>(wr, br, out);
}